// round 3
// baseline (speedup 1.0000x reference)
#include <cuda_runtime.h>
#include <cstdio>

#define Hh  8
#define Dd  256
#define HDe 32
#define Bb  16
#define Qq  512
#define S1c 64
#define Tt  448

// ---------------- static scratch (no allocations allowed) ----------------
__device__ float g_Qt1[Hh*Bb*Tt*HDe];
__device__ float g_Qt [Hh*Bb*Tt*HDe];
__device__ float g_Kc [Hh*Bb*Tt*HDe];
__device__ float g_Vc [Hh*Bb*Tt*HDe];
__device__ float g_Qs [Hh*Bb*S1c*HDe];
__device__ float g_Ks [Hh*Bb*S1c*HDe];
__device__ float g_Vs [Hh*Bb*S1c*HDe];
__device__ float g_P1 [Hh*Bb*Tt*Tt];     // scores -> probs (in place), attend1
__device__ float g_P2 [Hh*Bb*Tt*S1c];    // attend2
__device__ float g_P3 [Hh*Bb*S1c*Tt];    // attend3
__device__ float g_heads[Bb*Qq*Dd];      // [b][q][h][e]

struct ProjArgs {
    const float* W[4];
    float*       O[4];
};

// ---------------- projection GEMM: X[token,256] x W[h,256,32] -> O[h,b,n,32] ----
// grid.x = token tiles (BM=64), grid.y = sel*4 + coltile(64 of 256)
__global__ __launch_bounds__(256) void proj_kernel(
    const float* __restrict__ X, ProjArgs args, int TL, int qoff)
{
    __shared__ float As[32][64];  // [k][m]
    __shared__ float Bs[32][64];  // [k][n]
    const int sel = blockIdx.y >> 2;
    const int n0  = (blockIdx.y & 3) * 64;
    const int m0  = blockIdx.x * 64;
    const float* __restrict__ W = args.W[sel];
    float* __restrict__ O = args.O[sel];
    const int tid = threadIdx.x;
    const int tx = tid & 15, ty = tid >> 4;

    float acc[4][4];
#pragma unroll
    for (int i = 0; i < 4; i++)
#pragma unroll
        for (int j = 0; j < 4; j++) acc[i][j] = 0.f;

    int arow[2];
#pragma unroll
    for (int i = 0; i < 2; i++) {
        int lin = tid + i * 256;
        int m = lin >> 3;
        int t = m0 + m;
        int b = t / TL, n = t - b * TL;
        arow[i] = b * Qq + qoff + n;
    }

    for (int k0 = 0; k0 < Dd; k0 += 32) {
#pragma unroll
        for (int i = 0; i < 2; i++) {
            int lin = tid + i * 256;
            int m = lin >> 3;
            int kq = (lin & 7) << 2;
            float4 v = *(const float4*)(X + (size_t)arow[i] * Dd + k0 + kq);
            As[kq + 0][m] = v.x; As[kq + 1][m] = v.y;
            As[kq + 2][m] = v.z; As[kq + 3][m] = v.w;
        }
#pragma unroll
        for (int i = 0; i < 2; i++) {
            int lin = tid + i * 256;           // 512 float4 slots
            int kk = lin >> 4;
            int nq = (lin & 15) << 2;
            int c = n0 + nq;
            int h = c >> 5, e = c & 31;
            *(float4*)&Bs[kk][nq] =
                *(const float4*)(W + (size_t)h * (Dd * HDe) + (k0 + kk) * HDe + e);
        }
        __syncthreads();
#pragma unroll
        for (int kk = 0; kk < 32; kk++) {
            float a[4], bq[4];
            *(float4*)a  = *(const float4*)&As[kk][ty << 2];
            *(float4*)bq = *(const float4*)&Bs[kk][tx << 2];
#pragma unroll
            for (int i = 0; i < 4; i++)
#pragma unroll
                for (int j = 0; j < 4; j++)
                    acc[i][j] = fmaf(a[i], bq[j], acc[i][j]);
        }
        __syncthreads();
    }
    const int c = n0 + (tx << 2);
    const int h = c >> 5, e = c & 31;
#pragma unroll
    for (int i = 0; i < 4; i++) {
        int t = m0 + (ty << 2) + i;
        int b = t / TL, n = t - b * TL;
        float4 v = make_float4(acc[i][0], acc[i][1], acc[i][2], acc[i][3]);
        *(float4*)(O + (((size_t)h * Bb + b) * TL + n) * HDe + e) = v;
    }
}

// ---------------- batched QK^T: per z=(h*B+b): S[n,m] = Q[n,:]·K[m,:] (K=32) ----
__global__ __launch_bounds__(256) void qk_kernel(
    const float* __restrict__ Qm, const float* __restrict__ Km,
    float* __restrict__ S, int Nq, int Nk)
{
    __shared__ float Qs[32][64];  // [e][n]
    __shared__ float Ks[32][64];  // [e][m]
    const int z = blockIdx.z;
    const float* Qb = Qm + (size_t)z * Nq * HDe;
    const float* Kb = Km + (size_t)z * Nk * HDe;
    float* Sb = S + (size_t)z * Nq * Nk;
    const int mq0 = blockIdx.y * 64;
    const int mk0 = blockIdx.x * 64;
    const int tid = threadIdx.x;
#pragma unroll
    for (int i = 0; i < 2; i++) {
        int lin = tid + i * 256;
        int r = lin >> 3;
        int eq = (lin & 7) << 2;
        float4 v = *(const float4*)(Qb + (size_t)(mq0 + r) * HDe + eq);
        Qs[eq + 0][r] = v.x; Qs[eq + 1][r] = v.y;
        Qs[eq + 2][r] = v.z; Qs[eq + 3][r] = v.w;
        float4 w = *(const float4*)(Kb + (size_t)(mk0 + r) * HDe + eq);
        Ks[eq + 0][r] = w.x; Ks[eq + 1][r] = w.y;
        Ks[eq + 2][r] = w.z; Ks[eq + 3][r] = w.w;
    }
    __syncthreads();
    const int tx = tid & 15, ty = tid >> 4;
    float acc[4][4];
#pragma unroll
    for (int i = 0; i < 4; i++)
#pragma unroll
        for (int j = 0; j < 4; j++) acc[i][j] = 0.f;
#pragma unroll
    for (int e = 0; e < 32; e++) {
        float a[4], bq[4];
        *(float4*)a  = *(const float4*)&Qs[e][ty << 2];
        *(float4*)bq = *(const float4*)&Ks[e][tx << 2];
#pragma unroll
        for (int i = 0; i < 4; i++)
#pragma unroll
            for (int j = 0; j < 4; j++)
                acc[i][j] = fmaf(a[i], bq[j], acc[i][j]);
    }
#pragma unroll
    for (int i = 0; i < 4; i++) {
        float4 v = make_float4(acc[i][0], acc[i][1], acc[i][2], acc[i][3]);
        *(float4*)(Sb + (size_t)(mq0 + (ty << 2) + i) * Nk + mk0 + (tx << 2)) = v;
    }
}

// ---------------- fuse MLP + softmax (in place over S) --------------------
// CTA per (b, QPB queries). x=[s_0..7, aux_0..7] -> relu(x W1 + b1) W2 + b2 ; softmax over m.
template<int NK, int QPB>
__global__ __launch_bounds__(256) void fuse_softmax_kernel(
    float* __restrict__ S, const float* __restrict__ aux,
    const float* __restrict__ W1, const float* __restrict__ b1,
    const float* __restrict__ W2, const float* __restrict__ b2,
    int Nq, int qn_off, int qm_off)
{
    __shared__ float sW1t[256];  // transposed: sW1t[j*16+c] = W1[c][j]  -> float4 LDS
    __shared__ float sW2[128];   // [j][h] as stored
    __shared__ float sb1[16], sb2[8];
    __shared__ float fs[QPB][8][NK];
    const int tid = threadIdx.x;
    sW1t[tid] = W1[(tid & 15) * 16 + (tid >> 4)];
    if (tid < 128) sW2[tid] = W2[tid];
    if (tid < 16)  sb1[tid] = b1[tid];
    if (tid < 8)   sb2[tid] = b2[tid];
    __syncthreads();

    const int nblocks = Nq / QPB;
    const int nb = blockIdx.x % nblocks;
    const int b  = blockIdx.x / nblocks;
    constexpr int TPQ = 256 / QPB;
    const int ql = tid / TPQ;
    const int tl = tid % TPQ;
    const int n  = nb * QPB + ql;

    for (int m = tl; m < NK; m += TPQ) {
        float x[16];
#pragma unroll
        for (int h = 0; h < 8; h++) {
            x[h]     = S  [((size_t)(h * Bb + b) * Nq + n) * NK + m];
            x[8 + h] = aux[((size_t)(h * Bb + b) * Qq + qn_off + n) * Qq + qm_off + m];
        }
        float f[8];
#pragma unroll
        for (int h = 0; h < 8; h++) f[h] = sb2[h];
#pragma unroll
        for (int j = 0; j < 16; j++) {
            float4 wa = *(const float4*)&sW1t[j * 16 + 0];
            float4 wb = *(const float4*)&sW1t[j * 16 + 4];
            float4 wc = *(const float4*)&sW1t[j * 16 + 8];
            float4 wd = *(const float4*)&sW1t[j * 16 + 12];
            float hj = sb1[j];
            hj = fmaf(x[0],  wa.x, hj); hj = fmaf(x[1],  wa.y, hj);
            hj = fmaf(x[2],  wa.z, hj); hj = fmaf(x[3],  wa.w, hj);
            hj = fmaf(x[4],  wb.x, hj); hj = fmaf(x[5],  wb.y, hj);
            hj = fmaf(x[6],  wb.z, hj); hj = fmaf(x[7],  wb.w, hj);
            hj = fmaf(x[8],  wc.x, hj); hj = fmaf(x[9],  wc.y, hj);
            hj = fmaf(x[10], wc.z, hj); hj = fmaf(x[11], wc.w, hj);
            hj = fmaf(x[12], wd.x, hj); hj = fmaf(x[13], wd.y, hj);
            hj = fmaf(x[14], wd.z, hj); hj = fmaf(x[15], wd.w, hj);
            hj = fmaxf(hj, 0.f);
            float4 w2a = *(const float4*)&sW2[j * 8 + 0];
            float4 w2b = *(const float4*)&sW2[j * 8 + 4];
            f[0] = fmaf(hj, w2a.x, f[0]); f[1] = fmaf(hj, w2a.y, f[1]);
            f[2] = fmaf(hj, w2a.z, f[2]); f[3] = fmaf(hj, w2a.w, f[3]);
            f[4] = fmaf(hj, w2b.x, f[4]); f[5] = fmaf(hj, w2b.y, f[5]);
            f[6] = fmaf(hj, w2b.z, f[6]); f[7] = fmaf(hj, w2b.w, f[7]);
        }
#pragma unroll
        for (int h = 0; h < 8; h++) fs[ql][h][m] = f[h];
    }
    __syncthreads();

    const int warp = tid >> 5, lane = tid & 31;
#pragma unroll
    for (int rr = 0; rr < QPB; rr++) {
        int row = warp * QPB + rr;
        int qr = row >> 3;
        int hr = row & 7;
        float* frow = fs[qr][hr];
        float mx = -3.0e38f;
        for (int m = lane; m < NK; m += 32) mx = fmaxf(mx, frow[m]);
#pragma unroll
        for (int o = 16; o > 0; o >>= 1) mx = fmaxf(mx, __shfl_xor_sync(0xffffffffu, mx, o));
        float sum = 0.f;
        for (int m = lane; m < NK; m += 32) {
            float ev = __expf(frow[m] - mx);
            frow[m] = ev;
            sum += ev;
        }
#pragma unroll
        for (int o = 16; o > 0; o >>= 1) sum += __shfl_xor_sync(0xffffffffu, sum, o);
        float inv = 1.f / sum;
        int n2 = nb * QPB + qr;
        float* Srow = S + ((size_t)(hr * Bb + b) * Nq + n2) * NK;
        for (int m = lane; m < NK; m += 32) Srow[m] = frow[m] * inv;
    }
}

// ---------------- batched AV: O[n,e] = sum_m P[n,m] V[m,e], write heads ----
__global__ __launch_bounds__(256) void av_kernel(
    const float* __restrict__ P, const float* __restrict__ V,
    float* __restrict__ heads, int Nq, int Nk, int qoff, int accum)
{
    __shared__ float As[32][64];   // [m][n]
    __shared__ float Bs[32][HDe];  // [m][e]
    const int z = blockIdx.z;
    const int h = z >> 4, b = z & 15;
    const float* Pb = P + (size_t)z * Nq * Nk;
    const float* Vb = V + (size_t)z * Nk * HDe;
    const int n0 = blockIdx.y * 64;
    const int tid = threadIdx.x;
    const int e = tid & 31;
    const int rg = tid >> 5;
    float acc[8];
#pragma unroll
    for (int i = 0; i < 8; i++) acc[i] = 0.f;

    for (int k0 = 0; k0 < Nk; k0 += 32) {
#pragma unroll
        for (int i = 0; i < 2; i++) {
            int lin = tid + i * 256;
            int r = lin >> 3;
            int mq = (lin & 7) << 2;
            float4 v = *(const float4*)(Pb + (size_t)(n0 + r) * Nk + k0 + mq);
            As[mq + 0][r] = v.x; As[mq + 1][r] = v.y;
            As[mq + 2][r] = v.z; As[mq + 3][r] = v.w;
        }
        {
            int kk = tid >> 3;
            int eq = (tid & 7) << 2;
            *(float4*)&Bs[kk][eq] = *(const float4*)(Vb + (size_t)(k0 + kk) * HDe + eq);
        }
        __syncthreads();
#pragma unroll
        for (int kk = 0; kk < 32; kk++) {
            float bv = Bs[kk][e];
            float a0[8];
            *(float4*)&a0[0] = *(const float4*)&As[kk][rg * 8];
            *(float4*)&a0[4] = *(const float4*)&As[kk][rg * 8 + 4];
#pragma unroll
            for (int i = 0; i < 8; i++)
                acc[i] = fmaf(a0[i], bv, acc[i]);
        }
        __syncthreads();
    }
#pragma unroll
    for (int i = 0; i < 8; i++) {
        int n = n0 + rg * 8 + i;
        size_t addr = ((size_t)(b * Qq + qoff + n)) * Dd + h * HDe + e;
        if (accum) heads[addr] += acc[i];
        else       heads[addr] = acc[i];
    }
}

// ---------------- output GEMM: out[8192,256] = heads[8192,256] @ Wout[256,256] ----
__global__ __launch_bounds__(256) void out_kernel(
    const float* __restrict__ A, const float* __restrict__ Wo,
    float* __restrict__ Out)
{
    __shared__ float As[32][64];
    __shared__ float Bs[32][64];
    const int m0 = blockIdx.x * 64;
    const int n0 = blockIdx.y * 64;
    const int tid = threadIdx.x;
    const int tx = tid & 15, ty = tid >> 4;
    float acc[4][4];
#pragma unroll
    for (int i = 0; i < 4; i++)
#pragma unroll
        for (int j = 0; j < 4; j++) acc[i][j] = 0.f;

    for (int k0 = 0; k0 < Dd; k0 += 32) {
#pragma unroll
        for (int i = 0; i < 2; i++) {
            int lin = tid + i * 256;
            int m = lin >> 3;
            int kq = (lin & 7) << 2;
            float4 v = *(const float4*)(A + (size_t)(m0 + m) * Dd + k0 + kq);
            As[kq + 0][m] = v.x; As[kq + 1][m] = v.y;
            As[kq + 2][m] = v.z; As[kq + 3][m] = v.w;
        }
#pragma unroll
        for (int i = 0; i < 2; i++) {
            int lin = tid + i * 256;
            int kk = lin >> 4;
            int nq = (lin & 15) << 2;
            *(float4*)&Bs[kk][nq] = *(const float4*)(Wo + (size_t)(k0 + kk) * Dd + n0 + nq);
        }
        __syncthreads();
#pragma unroll
        for (int kk = 0; kk < 32; kk++) {
            float a[4], bq[4];
            *(float4*)a  = *(const float4*)&As[kk][ty << 2];
            *(float4*)bq = *(const float4*)&Bs[kk][tx << 2];
#pragma unroll
            for (int i = 0; i < 4; i++)
#pragma unroll
                for (int j = 0; j < 4; j++)
                    acc[i][j] = fmaf(a[i], bq[j], acc[i][j]);
        }
        __syncthreads();
    }
#pragma unroll
    for (int i = 0; i < 4; i++) {
        float4 v = make_float4(acc[i][0], acc[i][1], acc[i][2], acc[i][3]);
        *(float4*)(Out + (size_t)(m0 + (ty << 2) + i) * Dd + n0 + (tx << 2)) = v;
    }
}

// ---------------- launch ----------------
extern "C" void kernel_launch(void* const* d_in, const int* in_sizes, int n_in,
                              void* d_out, int out_size)
{
    const float* h_fea      = (const float*)d_in[0];
    const float* aux        = (const float*)d_in[1];
    const float* Wq_custom  = (const float*)d_in[2];
    const float* Wq_custom1 = (const float*)d_in[3];
    const float* Wk_custom  = (const float*)d_in[4];
    const float* Wv_custom  = (const float*)d_in[5];
    const float* Wq_charge1 = (const float*)d_in[6];
    const float* Wk_charge  = (const float*)d_in[7];
    const float* Wv_charge  = (const float*)d_in[8];
    const float* W1         = (const float*)d_in[9];
    const float* b1         = (const float*)d_in[10];
    const float* W2         = (const float*)d_in[11];
    const float* b2         = (const float*)d_in[12];
    const float* W_out      = (const float*)d_in[13];
    float* out = (float*)d_out;

    float *Qt1, *Qt, *Kc, *Vc, *Qs, *Ks, *Vs, *P1, *P2, *P3, *heads;
    cudaGetSymbolAddress((void**)&Qt1,   g_Qt1);
    cudaGetSymbolAddress((void**)&Qt,    g_Qt);
    cudaGetSymbolAddress((void**)&Kc,    g_Kc);
    cudaGetSymbolAddress((void**)&Vc,    g_Vc);
    cudaGetSymbolAddress((void**)&Qs,    g_Qs);
    cudaGetSymbolAddress((void**)&Ks,    g_Ks);
    cudaGetSymbolAddress((void**)&Vs,    g_Vs);
    cudaGetSymbolAddress((void**)&P1,    g_P1);
    cudaGetSymbolAddress((void**)&P2,    g_P2);
    cudaGetSymbolAddress((void**)&P3,    g_P3);
    cudaGetSymbolAddress((void**)&heads, g_heads);

    // projections: task (4 weight sets), stat (3 weight sets)
    ProjArgs pt;
    pt.W[0] = Wq_custom1; pt.O[0] = Qt1;
    pt.W[1] = Wq_custom;  pt.O[1] = Qt;
    pt.W[2] = Wk_custom;  pt.O[2] = Kc;
    pt.W[3] = Wv_custom;  pt.O[3] = Vc;
    proj_kernel<<<dim3(Bb * Tt / 64, 16), 256>>>(h_fea, pt, Tt, S1c);

    ProjArgs ps;
    ps.W[0] = Wq_charge1; ps.O[0] = Qs;
    ps.W[1] = Wk_charge;  ps.O[1] = Ks;
    ps.W[2] = Wv_charge;  ps.O[2] = Vs;
    ps.W[3] = Wq_charge1; ps.O[3] = Qs;  // unused (grid.y limited to 12)
    proj_kernel<<<dim3(Bb * S1c / 64, 12), 256>>>(h_fea, ps, S1c, 0);

    // QK^T batched per (h,b)
    qk_kernel<<<dim3(Tt / 64,  Tt / 64,  Hh * Bb), 256>>>(Qt1, Kc, P1, Tt,  Tt);
    qk_kernel<<<dim3(S1c / 64, Tt / 64,  Hh * Bb), 256>>>(Qt,  Ks, P2, Tt,  S1c);
    qk_kernel<<<dim3(Tt / 64,  S1c / 64, Hh * Bb), 256>>>(Qs,  Kc, P3, S1c, Tt);

    // fuse MLP + softmax (in place)
    fuse_softmax_kernel<448, 1><<<Bb * Tt,       256>>>(P1, aux, W1, b1, W2, b2, Tt,  S1c, S1c);
    fuse_softmax_kernel<64,  4><<<Bb * (Tt / 4), 256>>>(P2, aux, W1, b1, W2, b2, Tt,  S1c, 0);
    fuse_softmax_kernel<448, 1><<<Bb * S1c,      256>>>(P3, aux, W1, b1, W2, b2, S1c, 0,   S1c);

    // AV into heads[b,q,h,e]; attend2 accumulates onto attend1's rows
    av_kernel<<<dim3(1, Tt / 64,  Hh * Bb), 256>>>(P1, Vc, heads, Tt,  Tt,  S1c, 0);
    av_kernel<<<dim3(1, Tt / 64,  Hh * Bb), 256>>>(P2, Vs, heads, Tt,  S1c, S1c, 1);
    av_kernel<<<dim3(1, S1c / 64, Hh * Bb), 256>>>(P3, Vc, heads, S1c, Tt,  0,   0);

    // output projection (W_out[h][e][d] is exactly [256,256] row-major)
    out_kernel<<<dim3(Bb * Qq / 64, Dd / 64), 256>>>(heads, W_out, out);
}

// round 4
// speedup vs baseline: 1.7399x; 1.7399x over previous
#include <cuda_runtime.h>
#include <cstdio>

#define Hh  8
#define Dd  256
#define HDe 32
#define Bb  16
#define Qq  512
#define S1c 64
#define Tt  448

typedef unsigned long long u64;

// ---- packed f32x2 helpers (FFMA2 is PTX-only; ptxas never auto-fuses) ----
__device__ __forceinline__ u64 pk2(float x, float y) {
    u64 r; asm("mov.b64 %0, {%1, %2};" : "=l"(r) : "f"(x), "f"(y)); return r;
}
__device__ __forceinline__ float2 up2(u64 v) {
    float2 r; asm("mov.b64 {%0, %1}, %2;" : "=f"(r.x), "=f"(r.y) : "l"(v)); return r;
}
__device__ __forceinline__ u64 fma2(u64 a, u64 b, u64 c) {
    u64 d; asm("fma.rn.f32x2 %0, %1, %2, %3;" : "=l"(d) : "l"(a), "l"(b), "l"(c)); return d;
}

// ---------------- static scratch (no allocations allowed) ----------------
__device__ float g_Qt1[Hh*Bb*Tt*HDe];
__device__ float g_Qt [Hh*Bb*Tt*HDe];
__device__ float g_Kc [Hh*Bb*Tt*HDe];
__device__ float g_Vc [Hh*Bb*Tt*HDe];
__device__ float g_Qs [Hh*Bb*S1c*HDe];
__device__ float g_Ks [Hh*Bb*S1c*HDe];
__device__ float g_Vs [Hh*Bb*S1c*HDe];
__device__ float g_P1 [Hh*Bb*Tt*Tt];
__device__ float g_P2 [Hh*Bb*Tt*S1c];
__device__ float g_P3 [Hh*Bb*S1c*Tt];
__device__ float g_heads[Bb*Qq*Dd];      // [b][q][h][e]

struct ProjArgs {
    const float* W[4];
    float*       O[4];
};

// ---------------- projection GEMM: X[token,256] x W[h,256,32] -> O[h,b,n,32] ----
__global__ __launch_bounds__(256) void proj_kernel(
    const float* __restrict__ X, ProjArgs args, int TL, int qoff)
{
    __shared__ __align__(16) float As[32][64];  // [k][m]
    __shared__ __align__(16) float Bs[32][64];  // [k][n]
    const int sel = blockIdx.y >> 2;
    const int n0  = (blockIdx.y & 3) * 64;
    const int m0  = blockIdx.x * 64;
    const float* __restrict__ W = args.W[sel];
    float* __restrict__ O = args.O[sel];
    const int tid = threadIdx.x;
    const int tx = tid & 15, ty = tid >> 4;

    u64 acc2[4][2];
#pragma unroll
    for (int i = 0; i < 4; i++) { acc2[i][0] = 0ull; acc2[i][1] = 0ull; }

    int arow[2];
#pragma unroll
    for (int i = 0; i < 2; i++) {
        int lin = tid + i * 256;
        int m = lin >> 3;
        int t = m0 + m;
        int b = t / TL, n = t - b * TL;
        arow[i] = b * Qq + qoff + n;
    }

    for (int k0 = 0; k0 < Dd; k0 += 32) {
#pragma unroll
        for (int i = 0; i < 2; i++) {
            int lin = tid + i * 256;
            int m = lin >> 3;
            int kq = (lin & 7) << 2;
            float4 v = *(const float4*)(X + (size_t)arow[i] * Dd + k0 + kq);
            As[kq + 0][m] = v.x; As[kq + 1][m] = v.y;
            As[kq + 2][m] = v.z; As[kq + 3][m] = v.w;
        }
#pragma unroll
        for (int i = 0; i < 2; i++) {
            int lin = tid + i * 256;
            int kk = lin >> 4;
            int nq = (lin & 15) << 2;
            int c = n0 + nq;
            int h = c >> 5, e = c & 31;
            *(float4*)&Bs[kk][nq] =
                *(const float4*)(W + (size_t)h * (Dd * HDe) + (k0 + kk) * HDe + e);
        }
        __syncthreads();
#pragma unroll
        for (int kk = 0; kk < 32; kk++) {
            float4 a = *(const float4*)&As[kk][ty << 2];
            ulonglong2 bq = *(const ulonglong2*)&Bs[kk][tx << 2];
            u64 a0 = pk2(a.x, a.x), a1 = pk2(a.y, a.y);
            u64 a2 = pk2(a.z, a.z), a3 = pk2(a.w, a.w);
            acc2[0][0] = fma2(a0, bq.x, acc2[0][0]); acc2[0][1] = fma2(a0, bq.y, acc2[0][1]);
            acc2[1][0] = fma2(a1, bq.x, acc2[1][0]); acc2[1][1] = fma2(a1, bq.y, acc2[1][1]);
            acc2[2][0] = fma2(a2, bq.x, acc2[2][0]); acc2[2][1] = fma2(a2, bq.y, acc2[2][1]);
            acc2[3][0] = fma2(a3, bq.x, acc2[3][0]); acc2[3][1] = fma2(a3, bq.y, acc2[3][1]);
        }
        __syncthreads();
    }
    const int c = n0 + (tx << 2);
    const int h = c >> 5, e = c & 31;
#pragma unroll
    for (int i = 0; i < 4; i++) {
        int t = m0 + (ty << 2) + i;
        int b = t / TL, n = t - b * TL;
        ulonglong2 st; st.x = acc2[i][0]; st.y = acc2[i][1];
        *(ulonglong2*)(O + (((size_t)h * Bb + b) * TL + n) * HDe + e) = st;
    }
}

// ---------------- batched QK^T: per z=(h*B+b): S[n,m] = Q[n,:]·K[m,:] (K=32) ----
__global__ __launch_bounds__(256) void qk_kernel(
    const float* __restrict__ Qm, const float* __restrict__ Km,
    float* __restrict__ S, int Nq, int Nk)
{
    __shared__ __align__(16) float Qs[32][64];  // [e][n]
    __shared__ __align__(16) float Ks[32][64];  // [e][m]
    const int z = blockIdx.z;
    const float* Qb = Qm + (size_t)z * Nq * HDe;
    const float* Kb = Km + (size_t)z * Nk * HDe;
    float* Sb = S + (size_t)z * Nq * Nk;
    const int mq0 = blockIdx.y * 64;
    const int mk0 = blockIdx.x * 64;
    const int tid = threadIdx.x;
#pragma unroll
    for (int i = 0; i < 2; i++) {
        int lin = tid + i * 256;
        int r = lin >> 3;
        int eq = (lin & 7) << 2;
        float4 v = *(const float4*)(Qb + (size_t)(mq0 + r) * HDe + eq);
        Qs[eq + 0][r] = v.x; Qs[eq + 1][r] = v.y;
        Qs[eq + 2][r] = v.z; Qs[eq + 3][r] = v.w;
        float4 w = *(const float4*)(Kb + (size_t)(mk0 + r) * HDe + eq);
        Ks[eq + 0][r] = w.x; Ks[eq + 1][r] = w.y;
        Ks[eq + 2][r] = w.z; Ks[eq + 3][r] = w.w;
    }
    __syncthreads();
    const int tx = tid & 15, ty = tid >> 4;
    u64 acc2[4][2];
#pragma unroll
    for (int i = 0; i < 4; i++) { acc2[i][0] = 0ull; acc2[i][1] = 0ull; }
#pragma unroll
    for (int e = 0; e < 32; e++) {
        float4 a = *(const float4*)&Qs[e][ty << 2];
        ulonglong2 bq = *(const ulonglong2*)&Ks[e][tx << 2];
        u64 a0 = pk2(a.x, a.x), a1 = pk2(a.y, a.y);
        u64 a2 = pk2(a.z, a.z), a3 = pk2(a.w, a.w);
        acc2[0][0] = fma2(a0, bq.x, acc2[0][0]); acc2[0][1] = fma2(a0, bq.y, acc2[0][1]);
        acc2[1][0] = fma2(a1, bq.x, acc2[1][0]); acc2[1][1] = fma2(a1, bq.y, acc2[1][1]);
        acc2[2][0] = fma2(a2, bq.x, acc2[2][0]); acc2[2][1] = fma2(a2, bq.y, acc2[2][1]);
        acc2[3][0] = fma2(a3, bq.x, acc2[3][0]); acc2[3][1] = fma2(a3, bq.y, acc2[3][1]);
    }
#pragma unroll
    for (int i = 0; i < 4; i++) {
        ulonglong2 st; st.x = acc2[i][0]; st.y = acc2[i][1];
        *(ulonglong2*)(Sb + (size_t)(mq0 + (ty << 2) + i) * Nk + mk0 + (tx << 2)) = st;
    }
}

// ---------------- fuse MLP + softmax (in place over S), packed f32x2 --------
// Each thread handles 4 adjacent m as 2 packed lanes; weights pre-duplicated
// (w,w) in smem so every FMA operand is born packed (no per-iter MOVs).
template<int NK, int QPB>
__global__ __launch_bounds__(256) void fuse_softmax_kernel(
    float* __restrict__ S, const float* __restrict__ aux,
    const float* __restrict__ W1, const float* __restrict__ b1,
    const float* __restrict__ W2, const float* __restrict__ b2,
    int Nq, int qn_off, int qm_off)
{
    __shared__ __align__(16) u64 sW1d[16][16];  // sW1d[j][c] = dup(W1[c][j])
    __shared__ __align__(16) u64 sW2d[16][8];   // sW2d[j][h] = dup(W2[j][h])
    __shared__ u64 sb1d[16], sb2d[8];
    __shared__ __align__(16) float fs[QPB][8][NK];
    const int tid = threadIdx.x;
    { int j = tid >> 4, c = tid & 15; float w = W1[c * 16 + j]; sW1d[j][c] = pk2(w, w); }
    if (tid < 128) { int j = tid >> 3, h = tid & 7; float w = W2[j * 8 + h]; sW2d[j][h] = pk2(w, w); }
    if (tid < 16)  { float w = b1[tid]; sb1d[tid] = pk2(w, w); }
    if (tid < 8)   { float w = b2[tid]; sb2d[tid] = pk2(w, w); }
    __syncthreads();

    const int nblocks = Nq / QPB;
    const int nb = blockIdx.x % nblocks;
    const int b  = blockIdx.x / nblocks;
    constexpr int TPQ = 256 / QPB;
    const int ql = tid / TPQ;
    const int tl = tid % TPQ;
    const int n  = nb * QPB + ql;
    const int m0 = tl * 4;

    if (m0 < NK) {
        u64 x2[16][2];
#pragma unroll
        for (int h = 0; h < 8; h++) {
            ulonglong2 v = *(const ulonglong2*)(S + ((size_t)(h * Bb + b) * Nq + n) * NK + m0);
            x2[h][0] = v.x; x2[h][1] = v.y;
            ulonglong2 w = *(const ulonglong2*)(aux + ((size_t)(h * Bb + b) * Qq + qn_off + n) * Qq + qm_off + m0);
            x2[8 + h][0] = w.x; x2[8 + h][1] = w.y;
        }
        u64 f0[8], f1[8];
#pragma unroll
        for (int h = 0; h < 8; h++) { f0[h] = sb2d[h]; f1[h] = f0[h]; }
#pragma unroll
        for (int j = 0; j < 16; j++) {
            u64 h0 = sb1d[j], h1 = h0;
            ulonglong2 w1p[8];
#pragma unroll
            for (int p = 0; p < 8; p++) w1p[p] = *(const ulonglong2*)&sW1d[j][p * 2];
#pragma unroll
            for (int c = 0; c < 16; c++) {
                u64 wv = (c & 1) ? w1p[c >> 1].y : w1p[c >> 1].x;
                h0 = fma2(x2[c][0], wv, h0);
                h1 = fma2(x2[c][1], wv, h1);
            }
            float2 ra = up2(h0), rb = up2(h1);
            ra.x = fmaxf(ra.x, 0.f); ra.y = fmaxf(ra.y, 0.f);
            rb.x = fmaxf(rb.x, 0.f); rb.y = fmaxf(rb.y, 0.f);
            u64 r0 = pk2(ra.x, ra.y), r1 = pk2(rb.x, rb.y);
            ulonglong2 w2p[4];
#pragma unroll
            for (int p = 0; p < 4; p++) w2p[p] = *(const ulonglong2*)&sW2d[j][p * 2];
#pragma unroll
            for (int h = 0; h < 8; h++) {
                u64 wv = (h & 1) ? w2p[h >> 1].y : w2p[h >> 1].x;
                f0[h] = fma2(r0, wv, f0[h]);
                f1[h] = fma2(r1, wv, f1[h]);
            }
        }
#pragma unroll
        for (int h = 0; h < 8; h++) {
            ulonglong2 st; st.x = f0[h]; st.y = f1[h];
            *(ulonglong2*)&fs[ql][h][m0] = st;
        }
    }
    __syncthreads();

    const int warp = tid >> 5, lane = tid & 31;
    constexpr int R = QPB * 8;
    for (int row = warp; row < R; row += 8) {
        int qr = row >> 3;
        int hr = row & 7;
        float* frow = fs[qr][hr];
        float mx = -3.0e38f;
        for (int m = lane; m < NK; m += 32) mx = fmaxf(mx, frow[m]);
#pragma unroll
        for (int o = 16; o > 0; o >>= 1) mx = fmaxf(mx, __shfl_xor_sync(0xffffffffu, mx, o));
        float sum = 0.f;
        for (int m = lane; m < NK; m += 32) {
            float ev = __expf(frow[m] - mx);
            frow[m] = ev;
            sum += ev;
        }
#pragma unroll
        for (int o = 16; o > 0; o >>= 1) sum += __shfl_xor_sync(0xffffffffu, sum, o);
        float inv = 1.f / sum;
        float* Srow = S + ((size_t)(hr * Bb + b) * Nq + nb * QPB + qr) * NK;
        for (int m = lane; m < NK; m += 32) Srow[m] = frow[m] * inv;
    }
}

// ---------------- batched AV: O[n,e] = sum_m P[n,m] V[m,e], write heads ----
__global__ __launch_bounds__(256) void av_kernel(
    const float* __restrict__ P, const float* __restrict__ V,
    float* __restrict__ heads, int Nq, int Nk, int qoff, int accum)
{
    __shared__ __align__(16) float As[32][64];   // [m][n]
    __shared__ __align__(16) float Bs[32][HDe];  // [m][e]
    const int z = blockIdx.z;
    const int h = z >> 4, b = z & 15;
    const float* Pb = P + (size_t)z * Nq * Nk;
    const float* Vb = V + (size_t)z * Nk * HDe;
    const int n0 = blockIdx.y * 64;
    const int tid = threadIdx.x;
    const int e = tid & 31;
    const int rg = tid >> 5;
    u64 acc2[4];
#pragma unroll
    for (int i = 0; i < 4; i++) acc2[i] = 0ull;

    for (int k0 = 0; k0 < Nk; k0 += 32) {
#pragma unroll
        for (int i = 0; i < 2; i++) {
            int lin = tid + i * 256;
            int r = lin >> 3;
            int mq = (lin & 7) << 2;
            float4 v = *(const float4*)(Pb + (size_t)(n0 + r) * Nk + k0 + mq);
            As[mq + 0][r] = v.x; As[mq + 1][r] = v.y;
            As[mq + 2][r] = v.z; As[mq + 3][r] = v.w;
        }
        {
            int kk = tid >> 3;
            int eq = (tid & 7) << 2;
            *(float4*)&Bs[kk][eq] = *(const float4*)(Vb + (size_t)(k0 + kk) * HDe + eq);
        }
        __syncthreads();
#pragma unroll
        for (int kk = 0; kk < 32; kk++) {
            float bv = Bs[kk][e];
            u64 bd = pk2(bv, bv);
            ulonglong2 aa = *(const ulonglong2*)&As[kk][rg * 8];
            ulonglong2 ab = *(const ulonglong2*)&As[kk][rg * 8 + 4];
            acc2[0] = fma2(aa.x, bd, acc2[0]);
            acc2[1] = fma2(aa.y, bd, acc2[1]);
            acc2[2] = fma2(ab.x, bd, acc2[2]);
            acc2[3] = fma2(ab.y, bd, acc2[3]);
        }
        __syncthreads();
    }
#pragma unroll
    for (int p = 0; p < 4; p++) {
        float2 v = up2(acc2[p]);
        int n = n0 + rg * 8 + p * 2;
        size_t a0 = ((size_t)(b * Qq + qoff + n)) * Dd + h * HDe + e;
        size_t a1 = ((size_t)(b * Qq + qoff + n + 1)) * Dd + h * HDe + e;
        if (accum) { heads[a0] += v.x; heads[a1] += v.y; }
        else       { heads[a0] = v.x;  heads[a1] = v.y; }
    }
}

// ---------------- output GEMM: out[8192,256] = heads[8192,256] @ Wout[256,256] ----
__global__ __launch_bounds__(256) void out_kernel(
    const float* __restrict__ A, const float* __restrict__ Wo,
    float* __restrict__ Out)
{
    __shared__ __align__(16) float As[32][64];
    __shared__ __align__(16) float Bs[32][64];
    const int m0 = blockIdx.x * 64;
    const int n0 = blockIdx.y * 64;
    const int tid = threadIdx.x;
    const int tx = tid & 15, ty = tid >> 4;
    u64 acc2[4][2];
#pragma unroll
    for (int i = 0; i < 4; i++) { acc2[i][0] = 0ull; acc2[i][1] = 0ull; }

    for (int k0 = 0; k0 < Dd; k0 += 32) {
#pragma unroll
        for (int i = 0; i < 2; i++) {
            int lin = tid + i * 256;
            int m = lin >> 3;
            int kq = (lin & 7) << 2;
            float4 v = *(const float4*)(A + (size_t)(m0 + m) * Dd + k0 + kq);
            As[kq + 0][m] = v.x; As[kq + 1][m] = v.y;
            As[kq + 2][m] = v.z; As[kq + 3][m] = v.w;
        }
#pragma unroll
        for (int i = 0; i < 2; i++) {
            int lin = tid + i * 256;
            int kk = lin >> 4;
            int nq = (lin & 15) << 2;
            *(float4*)&Bs[kk][nq] = *(const float4*)(Wo + (size_t)(k0 + kk) * Dd + n0 + nq);
        }
        __syncthreads();
#pragma unroll
        for (int kk = 0; kk < 32; kk++) {
            float4 a = *(const float4*)&As[kk][ty << 2];
            ulonglong2 bq = *(const ulonglong2*)&Bs[kk][tx << 2];
            u64 a0 = pk2(a.x, a.x), a1 = pk2(a.y, a.y);
            u64 a2 = pk2(a.z, a.z), a3 = pk2(a.w, a.w);
            acc2[0][0] = fma2(a0, bq.x, acc2[0][0]); acc2[0][1] = fma2(a0, bq.y, acc2[0][1]);
            acc2[1][0] = fma2(a1, bq.x, acc2[1][0]); acc2[1][1] = fma2(a1, bq.y, acc2[1][1]);
            acc2[2][0] = fma2(a2, bq.x, acc2[2][0]); acc2[2][1] = fma2(a2, bq.y, acc2[2][1]);
            acc2[3][0] = fma2(a3, bq.x, acc2[3][0]); acc2[3][1] = fma2(a3, bq.y, acc2[3][1]);
        }
        __syncthreads();
    }
#pragma unroll
    for (int i = 0; i < 4; i++) {
        ulonglong2 st; st.x = acc2[i][0]; st.y = acc2[i][1];
        *(ulonglong2*)(Out + (size_t)(m0 + (ty << 2) + i) * Dd + n0 + (tx << 2)) = st;
    }
}

// ---------------- launch ----------------
extern "C" void kernel_launch(void* const* d_in, const int* in_sizes, int n_in,
                              void* d_out, int out_size)
{
    const float* h_fea      = (const float*)d_in[0];
    const float* aux        = (const float*)d_in[1];
    const float* Wq_custom  = (const float*)d_in[2];
    const float* Wq_custom1 = (const float*)d_in[3];
    const float* Wk_custom  = (const float*)d_in[4];
    const float* Wv_custom  = (const float*)d_in[5];
    const float* Wq_charge1 = (const float*)d_in[6];
    const float* Wk_charge  = (const float*)d_in[7];
    const float* Wv_charge  = (const float*)d_in[8];
    const float* W1         = (const float*)d_in[9];
    const float* b1         = (const float*)d_in[10];
    const float* W2         = (const float*)d_in[11];
    const float* b2         = (const float*)d_in[12];
    const float* W_out      = (const float*)d_in[13];
    float* out = (float*)d_out;

    float *Qt1, *Qt, *Kc, *Vc, *Qs, *Ks, *Vs, *P1, *P2, *P3, *heads;
    cudaGetSymbolAddress((void**)&Qt1,   g_Qt1);
    cudaGetSymbolAddress((void**)&Qt,    g_Qt);
    cudaGetSymbolAddress((void**)&Kc,    g_Kc);
    cudaGetSymbolAddress((void**)&Vc,    g_Vc);
    cudaGetSymbolAddress((void**)&Qs,    g_Qs);
    cudaGetSymbolAddress((void**)&Ks,    g_Ks);
    cudaGetSymbolAddress((void**)&Vs,    g_Vs);
    cudaGetSymbolAddress((void**)&P1,    g_P1);
    cudaGetSymbolAddress((void**)&P2,    g_P2);
    cudaGetSymbolAddress((void**)&P3,    g_P3);
    cudaGetSymbolAddress((void**)&heads, g_heads);

    // projections: task (4 weight sets), stat (3 weight sets)
    ProjArgs pt;
    pt.W[0] = Wq_custom1; pt.O[0] = Qt1;
    pt.W[1] = Wq_custom;  pt.O[1] = Qt;
    pt.W[2] = Wk_custom;  pt.O[2] = Kc;
    pt.W[3] = Wv_custom;  pt.O[3] = Vc;
    proj_kernel<<<dim3(Bb * Tt / 64, 16), 256>>>(h_fea, pt, Tt, S1c);

    ProjArgs ps;
    ps.W[0] = Wq_charge1; ps.O[0] = Qs;
    ps.W[1] = Wk_charge;  ps.O[1] = Ks;
    ps.W[2] = Wv_charge;  ps.O[2] = Vs;
    ps.W[3] = Wq_charge1; ps.O[3] = Qs;  // unused (grid.y limited to 12)
    proj_kernel<<<dim3(Bb * S1c / 64, 12), 256>>>(h_fea, ps, S1c, 0);

    // QK^T batched per (h,b)
    qk_kernel<<<dim3(Tt / 64,  Tt / 64,  Hh * Bb), 256>>>(Qt1, Kc, P1, Tt,  Tt);
    qk_kernel<<<dim3(S1c / 64, Tt / 64,  Hh * Bb), 256>>>(Qt,  Ks, P2, Tt,  S1c);
    qk_kernel<<<dim3(Tt / 64,  S1c / 64, Hh * Bb), 256>>>(Qs,  Kc, P3, S1c, Tt);

    // fuse MLP + softmax (in place)
    fuse_softmax_kernel<448, 2><<<Bb * (Tt / 2),  256>>>(P1, aux, W1, b1, W2, b2, Tt,  S1c, S1c);
    fuse_softmax_kernel<64, 16><<<Bb * (Tt / 16), 256>>>(P2, aux, W1, b1, W2, b2, Tt,  S1c, 0);
    fuse_softmax_kernel<448, 2><<<Bb * (S1c / 2), 256>>>(P3, aux, W1, b1, W2, b2, S1c, 0,   S1c);

    // AV into heads[b,q,h,e]; attend2 accumulates onto attend1's rows
    av_kernel<<<dim3(1, Tt / 64,  Hh * Bb), 256>>>(P1, Vc, heads, Tt,  Tt,  S1c, 0);
    av_kernel<<<dim3(1, Tt / 64,  Hh * Bb), 256>>>(P2, Vs, heads, Tt,  S1c, S1c, 1);
    av_kernel<<<dim3(1, S1c / 64, Hh * Bb), 256>>>(P3, Vc, heads, S1c, Tt,  0,   0);

    // output projection (W_out[h][e][d] is exactly [256,256] row-major)
    out_kernel<<<dim3(Bb * Qq / 64, Dd / 64), 256>>>(heads, W_out, out);
}